// round 10
// baseline (speedup 1.0000x reference)
#include <cuda_runtime.h>
#include <math.h>

// Problem shape (fixed by the reference)
#define NSAMP 2048
#define OBS   48
// Layers: (out, in)
// L0: 512 x 48   L1: 256 x 512   L2: 128 x 256   L3: 12 x 128

// Inter-layer activation scratch (device globals: allocation-free).
__device__ __align__(16) float g_a0[NSAMP * 512];
__device__ __align__(16) float g_a1[NSAMP * 256];
__device__ __align__(16) float g_a2[NSAMP * 128];

__device__ __forceinline__ float elu(float s) {
    return (s > 0.0f) ? s : (__expf(s) - 1.0f);
}

// ---------------------------------------------------------------------------
// L0: obs-norm fused with 512x48 layer. 4-lane groups: lane gl loads 3
// contiguous float4 of one row; warp covers 8 rows = 1536B fully coalesced;
// 2-deep row-batch unroll -> 6 independent loads/lane; 2 shuffle rounds only.
// 256 threads, 128 rows/CTA -> 4 CTAs/sample (grid 8192).
// ---------------------------------------------------------------------------
__global__ void __launch_bounds__(256)
k_l0(const float* __restrict__ obs, const float* __restrict__ mean,
     const float* __restrict__ stdv, const float* __restrict__ W0,
     const float* __restrict__ b0) {
    const int b  = blockIdx.x;
    const int n  = b >> 2;             // sample
    const int rb = (b & 3) * 128;      // row base within sample
    const int tid = threadIdx.x;

    __shared__ __align__(16) float xs[OBS];
    if (tid < OBS) {
        const int i = n * OBS + tid;
        float v = (obs[i] - mean[i]) / stdv[i];
        xs[tid] = fminf(fmaxf(v, -5.0f), 5.0f);
    }
    __syncthreads();

    const int wid  = tid >> 5;         // 8 warps
    const int lane = tid & 31;
    const int g    = lane >> 2;        // 8 row-groups per warp
    const int gl   = lane & 3;         // 4 lanes per row

    const float4* __restrict__ xv = reinterpret_cast<const float4*>(xs);
    const float4 v0 = xv[gl * 3 + 0];
    const float4 v1 = xv[gl * 3 + 1];
    const float4 v2 = xv[gl * 3 + 2];

    const float* __restrict__ W  = W0 + (size_t)n * 512 * 48;
    const float* __restrict__ bb = b0 + (size_t)n * 512;
    float* __restrict__ y = g_a0 + (size_t)n * 512;

    const int r0 = rb + wid * 16 + g;
    const int r1 = r0 + 8;

    const float4* __restrict__ Wr0 =
        reinterpret_cast<const float4*>(W + (size_t)r0 * 48) + gl * 3;
    const float4* __restrict__ Wr1 =
        reinterpret_cast<const float4*>(W + (size_t)r1 * 48) + gl * 3;

    float bias0 = 0.f, bias1 = 0.f;
    if (gl == 0) { bias0 = __ldcs(bb + r0); bias1 = __ldcs(bb + r1); }

    float4 a0 = __ldcs(Wr0 + 0), a1 = __ldcs(Wr0 + 1), a2 = __ldcs(Wr0 + 2);
    float4 c0 = __ldcs(Wr1 + 0), c1 = __ldcs(Wr1 + 1), c2 = __ldcs(Wr1 + 2);

    float s0 = fmaf(a0.x, v0.x, fmaf(a0.y, v0.y, fmaf(a0.z, v0.z, a0.w * v0.w)));
    s0 = fmaf(a1.x, v1.x, fmaf(a1.y, v1.y, fmaf(a1.z, v1.z, fmaf(a1.w, v1.w, s0))));
    s0 = fmaf(a2.x, v2.x, fmaf(a2.y, v2.y, fmaf(a2.z, v2.z, fmaf(a2.w, v2.w, s0))));
    float s1 = fmaf(c0.x, v0.x, fmaf(c0.y, v0.y, fmaf(c0.z, v0.z, c0.w * v0.w)));
    s1 = fmaf(c1.x, v1.x, fmaf(c1.y, v1.y, fmaf(c1.z, v1.z, fmaf(c1.w, v1.w, s1))));
    s1 = fmaf(c2.x, v2.x, fmaf(c2.y, v2.y, fmaf(c2.z, v2.z, fmaf(c2.w, v2.w, s1))));

    s0 += __shfl_xor_sync(0xffffffffu, s0, 1);
    s1 += __shfl_xor_sync(0xffffffffu, s1, 1);
    s0 += __shfl_xor_sync(0xffffffffu, s0, 2);
    s1 += __shfl_xor_sync(0xffffffffu, s1, 2);

    if (gl == 0) {
        y[r0] = elu(s0 + bias0);
        y[r1] = elu(s1 + bias1);
    }
}

// ---------------------------------------------------------------------------
// Generic hidden layer: OUT x IN, warp per row-pair, ROWS_PER_CTA rows/CTA.
// 256 threads = 8 warps -> 16 rows per pass.
// ---------------------------------------------------------------------------
template <int OUT, int IN, int ROWS_PER_CTA, bool ACT>
__global__ void __launch_bounds__(256, 8)
k_layer(const float* __restrict__ Wg, const float* __restrict__ bg,
        const float* __restrict__ xg, float* __restrict__ yg) {
    constexpr int CTAS_PER_SAMPLE = OUT / ROWS_PER_CTA;
    constexpr int NV = IN / 4;
    const int b  = blockIdx.x;
    const int n  = b / CTAS_PER_SAMPLE;
    const int rb = (b % CTAS_PER_SAMPLE) * ROWS_PER_CTA;
    const int tid = threadIdx.x;
    const int wid = tid >> 5;          // 8 warps
    const int gl  = tid & 31;

    __shared__ __align__(16) float xs[IN];
    {
        const float4* __restrict__ src =
            reinterpret_cast<const float4*>(xg + (size_t)n * IN);
        if (tid < NV) reinterpret_cast<float4*>(xs)[tid] = src[tid];
    }
    __syncthreads();

    const float4* __restrict__ xv = reinterpret_cast<const float4*>(xs);
    const float* __restrict__ W = Wg + (size_t)n * OUT * IN;
    const float* __restrict__ bb = bg + (size_t)n * OUT;
    float* __restrict__ y = yg + (size_t)n * OUT;

    #pragma unroll
    for (int r0 = rb + wid; r0 < rb + ROWS_PER_CTA; r0 += 16) {
        const int r1 = r0 + 8;
        float bias0 = __ldcs(bb + r0);
        float bias1 = __ldcs(bb + r1);
        const float4* __restrict__ Wr0 =
            reinterpret_cast<const float4*>(W + (size_t)r0 * IN);
        const float4* __restrict__ Wr1 =
            reinterpret_cast<const float4*>(W + (size_t)r1 * IN);
        float s0 = 0.0f, s1 = 0.0f;
        #pragma unroll
        for (int j = gl; j < NV; j += 32) {
            float4 w0 = __ldcs(Wr0 + j);
            float4 w1 = __ldcs(Wr1 + j);
            float4 v  = xv[j];
            s0 = fmaf(w0.x, v.x, s0);
            s0 = fmaf(w0.y, v.y, s0);
            s0 = fmaf(w0.z, v.z, s0);
            s0 = fmaf(w0.w, v.w, s0);
            s1 = fmaf(w1.x, v.x, s1);
            s1 = fmaf(w1.y, v.y, s1);
            s1 = fmaf(w1.z, v.z, s1);
            s1 = fmaf(w1.w, v.w, s1);
        }
        #pragma unroll
        for (int o = 16; o >= 1; o >>= 1) {
            s0 += __shfl_xor_sync(0xffffffffu, s0, o);
            s1 += __shfl_xor_sync(0xffffffffu, s1, o);
        }
        if (gl == 0) {
            s0 += bias0;
            s1 += bias1;
            if (ACT) { s0 = elu(s0); s1 = elu(s1); }
            y[r0] = s0;
            y[r1] = s1;
        }
    }
}

// ---------------------------------------------------------------------------
// L3: 12 x 128 + tanh. One CTA (128 thr, 4 warps) per sample; warp w does
// rows {w, w+4, w+8}. Each lane: 1 x-load + 3 W-loads + bias, all independent.
// 262k resident threads -> ~40x the in-flight bytes of warp-per-sample.
// No shared memory, no __syncthreads.
// ---------------------------------------------------------------------------
__global__ void __launch_bounds__(128)
k_l3(const float* __restrict__ W3, const float* __restrict__ b3,
     float* __restrict__ out) {
    const int n    = blockIdx.x;
    const int tid  = threadIdx.x;
    const int wid  = tid >> 5;         // 4 warps
    const int lane = tid & 31;

    const float4* __restrict__ xv =
        reinterpret_cast<const float4*>(g_a2 + (size_t)n * 128);
    const float4* __restrict__ Wv =
        reinterpret_cast<const float4*>(W3 + (size_t)n * 12 * 128);
    const float* __restrict__ bb = b3 + (size_t)n * 12;

    // Rows for this warp
    const int r0 = wid, r1 = wid + 4, r2 = wid + 8;

    float bias0 = __ldcs(bb + r0);
    float bias1 = __ldcs(bb + r1);
    float bias2 = __ldcs(bb + r2);

    float4 v  = xv[lane];
    float4 w0 = __ldcs(Wv + r0 * 32 + lane);
    float4 w1 = __ldcs(Wv + r1 * 32 + lane);
    float4 w2 = __ldcs(Wv + r2 * 32 + lane);

    float s0 = fmaf(w0.x, v.x, fmaf(w0.y, v.y, fmaf(w0.z, v.z, w0.w * v.w)));
    float s1 = fmaf(w1.x, v.x, fmaf(w1.y, v.y, fmaf(w1.z, v.z, w1.w * v.w)));
    float s2 = fmaf(w2.x, v.x, fmaf(w2.y, v.y, fmaf(w2.z, v.z, w2.w * v.w)));

    #pragma unroll
    for (int o = 16; o >= 1; o >>= 1) {
        s0 += __shfl_xor_sync(0xffffffffu, s0, o);
        s1 += __shfl_xor_sync(0xffffffffu, s1, o);
        s2 += __shfl_xor_sync(0xffffffffu, s2, o);
    }

    if (lane == 0) {
        out[n * 12 + r0] = tanhf(s0 + bias0);
        out[n * 12 + r1] = tanhf(s1 + bias1);
        out[n * 12 + r2] = tanhf(s2 + bias2);
    }
}

extern "C" void kernel_launch(void* const* d_in, const int* in_sizes, int n_in,
                              void* d_out, int out_size) {
    const float* obs  = (const float*)d_in[0];
    const float* mean = (const float*)d_in[1];
    const float* stdv = (const float*)d_in[2];
    const float* W0   = (const float*)d_in[3];
    const float* b0   = (const float*)d_in[4];
    const float* W1   = (const float*)d_in[5];
    const float* b1   = (const float*)d_in[6];
    const float* W2   = (const float*)d_in[7];
    const float* b2   = (const float*)d_in[8];
    const float* W3   = (const float*)d_in[9];
    const float* b3   = (const float*)d_in[10];
    float* out = (float*)d_out;

    float* a0;  cudaGetSymbolAddress((void**)&a0, g_a0);
    float* a1;  cudaGetSymbolAddress((void**)&a1, g_a1);
    float* a2;  cudaGetSymbolAddress((void**)&a2, g_a2);

    // L0: 4 CTAs/sample (4-lane-group streaming)
    k_l0<<<NSAMP * 4, 256>>>(obs, mean, stdv, W0, b0);
    // L1: 256x512, 32 rows/CTA -> 8 CTAs/sample
    k_layer<256, 512, 32, true><<<NSAMP * 8, 256>>>(W1, b1, a0, a1);
    // L2: 128x256, 16 rows/CTA -> 8 CTAs/sample
    k_layer<128, 256, 16, true><<<NSAMP * 8, 256>>>(W2, b2, a1, a2);
    // L3: 12x128 + tanh, CTA/sample, 4 warps each
    k_l3<<<NSAMP, 128>>>(W3, b3, out);
}